// round 1
// baseline (speedup 1.0000x reference)
#include <cuda_runtime.h>
#include <math.h>

// Problem constants
constexpr int Bb = 2;
constexpr int Tt = 2048;
constexpr int Cc = 1024;
constexpr int Hh = 16;
constexpr int Dd = 64;
constexpr int Mrows = Bb * Tt;        // 4096
constexpr int C3 = 3 * Cc;            // 3072
constexpr int BH = Bb * Hh;           // 32

// Device scratch (allocation-free rule: __device__ globals)
__device__ float g_qkv[(size_t)Mrows * C3];    // [4096, 3072] = 50.3 MB
__device__ float g_attnv[(size_t)Mrows * Cc];  // [4096, 1024] = 16.8 MB

// ---------------------------------------------------------------------------
// Generic fp32 SGEMM with bias: C[M,N] = A[M,K] @ B[K,N] + bias[N]
// 128x128 tile, BK=8, 256 threads, 8x8 per thread. M,N multiples of 128,
// K multiple of 8 (true for all uses here).
// ---------------------------------------------------------------------------
__global__ __launch_bounds__(256) void sgemm_bias_128(
    const float* __restrict__ A, const float* __restrict__ Bm,
    const float* __restrict__ bias, float* __restrict__ Cm,
    int Md, int Nd, int Kd)
{
    constexpr int BM = 128, BN = 128, BK = 8, TM = 8, TN = 8;
    __shared__ float As[BK][BM];
    __shared__ float Bs[BK][BN];
    const int tid  = threadIdx.x;
    const int trow = tid / 16;
    const int tcol = tid % 16;
    const int row0 = blockIdx.y * BM;
    const int col0 = blockIdx.x * BN;

    const int arow = tid >> 1, acol = (tid & 1) * 4;   // A tile 128x8
    const int brow = tid >> 5, bcol = (tid & 31) * 4;  // B tile 8x128

    float acc[TM][TN] = {};

    for (int k0 = 0; k0 < Kd; k0 += BK) {
        float4 av = *(const float4*)(A + (size_t)(row0 + arow) * Kd + k0 + acol);
        As[acol + 0][arow] = av.x;
        As[acol + 1][arow] = av.y;
        As[acol + 2][arow] = av.z;
        As[acol + 3][arow] = av.w;
        float4 bv = *(const float4*)(Bm + (size_t)(k0 + brow) * Nd + col0 + bcol);
        *(float4*)&Bs[brow][bcol] = bv;
        __syncthreads();
#pragma unroll
        for (int k = 0; k < BK; k++) {
            float ra[TM], rb[TN];
#pragma unroll
            for (int i = 0; i < TM; i++) ra[i] = As[k][trow * TM + i];
#pragma unroll
            for (int j = 0; j < TN; j++) rb[j] = Bs[k][tcol * TN + j];
#pragma unroll
            for (int i = 0; i < TM; i++)
#pragma unroll
                for (int j = 0; j < TN; j++) acc[i][j] += ra[i] * rb[j];
        }
        __syncthreads();
    }

#pragma unroll
    for (int i = 0; i < TM; i++) {
        const int r = row0 + trow * TM + i;
#pragma unroll
        for (int j = 0; j < TN; j += 4) {
            const int c = col0 + tcol * TN + j;
            float4 o;
            o.x = acc[i][j + 0] + bias[c + 0];
            o.y = acc[i][j + 1] + bias[c + 1];
            o.z = acc[i][j + 2] + bias[c + 2];
            o.w = acc[i][j + 3] + bias[c + 3];
            *(float4*)(Cm + (size_t)r * Nd + c) = o;
        }
    }
}

// ---------------------------------------------------------------------------
// Scores: S[bh, q, k] = scale * sum_d Q[b,q,h,d] * K[b,k,h,d], causal -inf
// Per (b,h): 2048x2048 output, inner dim 64. 128x128 tiles.
// Fully-masked tiles get -inf without compute.
// ---------------------------------------------------------------------------
__global__ __launch_bounds__(256) void scores_kernel(float* __restrict__ S)
{
    constexpr int BM = 128, BN = 128, BK = 8, TM = 8, TN = 8;
    const int bh = blockIdx.z;
    const int b  = bh / Hh;
    const int h  = bh % Hh;
    const int q0 = blockIdx.y * BM;
    const int k0t = blockIdx.x * BN;
    float* Sb = S + (size_t)bh * Tt * Tt;
    const int tid = threadIdx.x;
    const float scale = 0.125f;  // 1/sqrt(64)

    if (k0t > q0 + BM - 1) {
        // fully above the diagonal: all masked
        for (int i = 0; i < 64; i++) {
            const int idx = i * 256 + tid;       // 128*128 elements
            const int r = idx >> 7, c = idx & 127;
            Sb[(size_t)(q0 + r) * Tt + k0t + c] = -INFINITY;
        }
        return;
    }

    __shared__ float Qs[BK][BM];
    __shared__ float Ks[BK][BN];
    const int trow = tid / 16, tcol = tid % 16;
    const int arow = tid >> 1, acol = (tid & 1) * 4;

    const float* Qb = g_qkv + (size_t)(b * Tt + q0) * C3 + h * Dd;           // q slice
    const float* Kb = g_qkv + (size_t)(b * Tt + k0t) * C3 + Cc + h * Dd;     // k slice

    float acc[TM][TN] = {};

    for (int d0 = 0; d0 < Dd; d0 += BK) {
        float4 qv = *(const float4*)(Qb + (size_t)arow * C3 + d0 + acol);
        Qs[acol + 0][arow] = qv.x;
        Qs[acol + 1][arow] = qv.y;
        Qs[acol + 2][arow] = qv.z;
        Qs[acol + 3][arow] = qv.w;
        float4 kv = *(const float4*)(Kb + (size_t)arow * C3 + d0 + acol);
        Ks[acol + 0][arow] = kv.x;
        Ks[acol + 1][arow] = kv.y;
        Ks[acol + 2][arow] = kv.z;
        Ks[acol + 3][arow] = kv.w;
        __syncthreads();
#pragma unroll
        for (int k = 0; k < BK; k++) {
            float ra[TM], rb[TN];
#pragma unroll
            for (int i = 0; i < TM; i++) ra[i] = Qs[k][trow * TM + i];
#pragma unroll
            for (int j = 0; j < TN; j++) rb[j] = Ks[k][tcol * TN + j];
#pragma unroll
            for (int i = 0; i < TM; i++)
#pragma unroll
                for (int j = 0; j < TN; j++) acc[i][j] += ra[i] * rb[j];
        }
        __syncthreads();
    }

#pragma unroll
    for (int i = 0; i < TM; i++) {
        const int q = q0 + trow * TM + i;
#pragma unroll
        for (int j = 0; j < TN; j++) {
            const int k = k0t + tcol * TN + j;
            Sb[(size_t)q * Tt + k] = (q >= k) ? acc[i][j] * scale : -INFINITY;
        }
    }
}

// ---------------------------------------------------------------------------
// Row softmax in place over rows of length T=2048. One block per row,
// 256 threads, 8 elements/thread. Masked entries (-inf) become exact 0.
// ---------------------------------------------------------------------------
__global__ __launch_bounds__(256) void softmax_kernel(float* __restrict__ S)
{
    const size_t row = blockIdx.x;
    float* p = S + row * (size_t)Tt;
    const int tid = threadIdx.x;
    __shared__ float red[8];

    float v[8];
    float mx = -INFINITY;
#pragma unroll
    for (int i = 0; i < 8; i++) {
        v[i] = p[tid + i * 256];
        mx = fmaxf(mx, v[i]);
    }
#pragma unroll
    for (int o = 16; o; o >>= 1) mx = fmaxf(mx, __shfl_xor_sync(0xffffffffu, mx, o));
    if ((tid & 31) == 0) red[tid >> 5] = mx;
    __syncthreads();
    float rowmax = red[0];
#pragma unroll
    for (int w = 1; w < 8; w++) rowmax = fmaxf(rowmax, red[w]);
    __syncthreads();

    float s = 0.f;
#pragma unroll
    for (int i = 0; i < 8; i++) {
        v[i] = __expf(v[i] - rowmax);   // exp(-inf - finite) = 0
        s += v[i];
    }
#pragma unroll
    for (int o = 16; o; o >>= 1) s += __shfl_xor_sync(0xffffffffu, s, o);
    if ((tid & 31) == 0) red[tid >> 5] = s;
    __syncthreads();
    float rowsum = 0.f;
#pragma unroll
    for (int w = 0; w < 8; w++) rowsum += red[w];
    const float inv = 1.0f / rowsum;
#pragma unroll
    for (int i = 0; i < 8; i++) p[tid + i * 256] = v[i] * inv;
}

// ---------------------------------------------------------------------------
// PV: attnv[b,q,h,d] = sum_k P[bh,q,k] * V[b,k,h,d].
// Tiles: 128 q-rows x 64 d-cols per block; causal truncates the k loop.
// ---------------------------------------------------------------------------
__global__ __launch_bounds__(256) void pv_kernel(const float* __restrict__ S)
{
    constexpr int BM = 128, BN = 64, BK = 8, TM = 8, TN = 4;
    const int q0 = blockIdx.x * BM;
    const int bh = blockIdx.y;
    const int b = bh / Hh, h = bh % Hh;
    const int tid = threadIdx.x;
    const int trow = tid / 16, tcol = tid % 16;

    __shared__ float Ps[BK][BM];
    __shared__ float Vs[BK][BN];

    const float* Sb = S + (size_t)bh * Tt * Tt + (size_t)q0 * Tt;
    const float* Vb = g_qkv + (size_t)(b * Tt) * C3 + 2 * Cc + h * Dd;

    const int arow = tid >> 1, acol = (tid & 1) * 4;   // P tile 128x8
    const int vrow = tid >> 5, vcol = (tid & 31) * 2;  // V tile 8x64

    float acc[TM][TN] = {};
    const int kmax = q0 + BM;  // rows in this tile need k <= q0+127

    for (int k0 = 0; k0 < kmax; k0 += BK) {
        float4 pv = *(const float4*)(Sb + (size_t)arow * Tt + k0 + acol);
        Ps[acol + 0][arow] = pv.x;
        Ps[acol + 1][arow] = pv.y;
        Ps[acol + 2][arow] = pv.z;
        Ps[acol + 3][arow] = pv.w;
        float2 vv = *(const float2*)(Vb + (size_t)(k0 + vrow) * C3 + vcol);
        Vs[vrow][vcol + 0] = vv.x;
        Vs[vrow][vcol + 1] = vv.y;
        __syncthreads();
#pragma unroll
        for (int k = 0; k < BK; k++) {
            float ra[TM], rb[TN];
#pragma unroll
            for (int i = 0; i < TM; i++) ra[i] = Ps[k][trow * TM + i];
#pragma unroll
            for (int j = 0; j < TN; j++) rb[j] = Vs[k][tcol * TN + j];
#pragma unroll
            for (int i = 0; i < TM; i++)
#pragma unroll
                for (int j = 0; j < TN; j++) acc[i][j] += ra[i] * rb[j];
        }
        __syncthreads();
    }

#pragma unroll
    for (int i = 0; i < TM; i++) {
        const int q = q0 + trow * TM + i;
#pragma unroll
        for (int j = 0; j < TN; j += 4) {
            const int d = tcol * TN + j;
            float4 o;
            o.x = acc[i][j + 0];
            o.y = acc[i][j + 1];
            o.z = acc[i][j + 2];
            o.w = acc[i][j + 3];
            *(float4*)(g_attnv + (size_t)(b * Tt + q) * Cc + h * Dd + d) = o;
        }
    }
}

// ---------------------------------------------------------------------------
extern "C" void kernel_launch(void* const* d_in, const int* in_sizes, int n_in,
                              void* d_out, int out_size)
{
    const float* x     = (const float*)d_in[0];
    const float* w_qkv = (const float*)d_in[1];
    const float* b_qkv = (const float*)d_in[2];
    const float* w_o   = (const float*)d_in[3];
    const float* b_o   = (const float*)d_in[4];

    float* out   = (float*)d_out;
    float* attnw = out + (size_t)Mrows * Cc;   // [o | attn_w] concatenation

    float* qkv_ptr   = nullptr;
    float* attnv_ptr = nullptr;
    cudaGetSymbolAddress((void**)&qkv_ptr,   g_qkv);
    cudaGetSymbolAddress((void**)&attnv_ptr, g_attnv);

    // 1) QKV projection: [4096,1024] @ [1024,3072] + b
    {
        dim3 grid(C3 / 128, Mrows / 128);
        sgemm_bias_128<<<grid, 256>>>(x, w_qkv, b_qkv, qkv_ptr, Mrows, C3, Cc);
    }
    // 2) Scores (causal masked) into d_out attn_w region
    {
        dim3 grid(Tt / 128, Tt / 128, BH);
        scores_kernel<<<grid, 256>>>(attnw);
    }
    // 3) Softmax in place
    {
        softmax_kernel<<<(unsigned)(BH * Tt), 256>>>(attnw);
    }
    // 4) P @ V
    {
        dim3 grid(Tt / 128, BH);
        pv_kernel<<<grid, 256>>>(attnw);
    }
    // 5) Output projection: [4096,1024] @ [1024,1024] + b -> o
    {
        dim3 grid(Cc / 128, Mrows / 128);
        sgemm_bias_128<<<grid, 256>>>(attnv_ptr, w_o, b_o, out, Mrows, Cc, Cc);
    }
}

// round 2
// speedup vs baseline: 2.3057x; 2.3057x over previous
#include <cuda_runtime.h>
#include <math.h>
#include <stdint.h>

// Problem constants
constexpr int Bb = 2;
constexpr int Tt = 2048;
constexpr int Cc = 1024;
constexpr int Hh = 16;
constexpr int Dd = 64;
constexpr int Mrows = Bb * Tt;        // 4096
constexpr int C3 = 3 * Cc;            // 3072
constexpr int BH = Bb * Hh;           // 32

// Device scratch (allocation-free rule: __device__ globals)
__device__ float g_qkv[(size_t)Mrows * C3];    // [4096, 3072]
__device__ float g_attnv[(size_t)Mrows * Cc];  // [4096, 1024]

// ---------------------------------------------------------------------------
// tf32 helpers
// ---------------------------------------------------------------------------
__device__ __forceinline__ uint32_t f2tf(float f) {
    uint32_t u;
    asm("cvt.rna.tf32.f32 %0, %1;" : "=r"(u) : "f"(f));
    return u;
}

__device__ __forceinline__ void mma8(float* c, const uint32_t* a, const uint32_t* b) {
    asm volatile(
        "mma.sync.aligned.m16n8k8.row.col.f32.tf32.tf32.f32 "
        "{%0,%1,%2,%3},{%4,%5,%6,%7},{%8,%9},{%0,%1,%2,%3};"
        : "+f"(c[0]), "+f"(c[1]), "+f"(c[2]), "+f"(c[3])
        : "r"(a[0]), "r"(a[1]), "r"(a[2]), "r"(a[3]), "r"(b[0]), "r"(b[1]));
}

// ---------------------------------------------------------------------------
// Generic NN GEMM: C[M,N] = A[M,K] @ B[K,N] + bias[N]   (tf32 HMMA)
// Block 128x128, BK=16, 256 threads = 8 warps (2 m x 4 n), warp tile 64x32.
// ---------------------------------------------------------------------------
__global__ __launch_bounds__(256) void gemm_nn_tf32(
    const float* __restrict__ A, int lda,
    const float* __restrict__ Bm, int ldb,
    const float* __restrict__ bias,
    float* __restrict__ Cm, int ldc, int Kd)
{
    __shared__ uint32_t As[128 * 20];   // [m][k], stride 20 (pad 4) -> conflict-free frags
    __shared__ uint32_t Bs[16 * 128];   // [k][n ^ ((k&3)<<3)] xor-swizzled

    const int tid = threadIdx.x;
    const int wid = tid >> 5, lane = tid & 31;
    const int g = lane >> 2, tg = lane & 3;
    const int warp_m = wid & 1, warp_n = wid >> 1;
    const int row0 = blockIdx.y * 128;
    const int col0 = blockIdx.x * 128;

    float acc[4][4][4] = {};

    for (int k0 = 0; k0 < Kd; k0 += 16) {
        // stage A tile 128x16
#pragma unroll
        for (int i = 0; i < 2; i++) {
            int f = tid + i * 256;
            int m = f >> 2, kq = (f & 3) * 4;
            float4 v = *(const float4*)(A + (size_t)(row0 + m) * lda + k0 + kq);
            As[m * 20 + kq + 0] = f2tf(v.x);
            As[m * 20 + kq + 1] = f2tf(v.y);
            As[m * 20 + kq + 2] = f2tf(v.z);
            As[m * 20 + kq + 3] = f2tf(v.w);
        }
        // stage B tile 16x128
#pragma unroll
        for (int i = 0; i < 2; i++) {
            int f = tid + i * 256;
            int k = f >> 5, nq = (f & 31) * 4;
            float4 v = *(const float4*)(Bm + (size_t)(k0 + k) * ldb + col0 + nq);
            int nx = nq ^ ((k & 3) << 3);
            Bs[k * 128 + nx + 0] = f2tf(v.x);
            Bs[k * 128 + nx + 1] = f2tf(v.y);
            Bs[k * 128 + nx + 2] = f2tf(v.z);
            Bs[k * 128 + nx + 3] = f2tf(v.w);
        }
        __syncthreads();

#pragma unroll
        for (int ks = 0; ks < 16; ks += 8) {
            uint32_t af[4][4], bf[4][2];
#pragma unroll
            for (int mi = 0; mi < 4; mi++) {
                int m = warp_m * 64 + mi * 16;
                af[mi][0] = As[(m + g) * 20 + ks + tg];
                af[mi][1] = As[(m + g + 8) * 20 + ks + tg];
                af[mi][2] = As[(m + g) * 20 + ks + tg + 4];
                af[mi][3] = As[(m + g + 8) * 20 + ks + tg + 4];
            }
            const int xr = tg << 3;
#pragma unroll
            for (int ni = 0; ni < 4; ni++) {
                int n = warp_n * 32 + ni * 8;
                bf[ni][0] = Bs[(ks + tg) * 128 + ((n + g) ^ xr)];
                bf[ni][1] = Bs[(ks + tg + 4) * 128 + ((n + g) ^ xr)];
            }
#pragma unroll
            for (int mi = 0; mi < 4; mi++)
#pragma unroll
                for (int ni = 0; ni < 4; ni++) mma8(acc[mi][ni], af[mi], bf[ni]);
        }
        __syncthreads();
    }

#pragma unroll
    for (int mi = 0; mi < 4; mi++) {
#pragma unroll
        for (int ni = 0; ni < 4; ni++) {
            int m = row0 + warp_m * 64 + mi * 16 + g;
            int n = col0 + warp_n * 32 + ni * 8 + tg * 2;
            float2 o0 = {acc[mi][ni][0] + bias[n], acc[mi][ni][1] + bias[n + 1]};
            float2 o1 = {acc[mi][ni][2] + bias[n], acc[mi][ni][3] + bias[n + 1]};
            *(float2*)(Cm + (size_t)m * ldc + n) = o0;
            *(float2*)(Cm + (size_t)(m + 8) * ldc + n) = o1;
        }
    }
}

// ---------------------------------------------------------------------------
// Scores: S[bh,q,k] = 0.125 * Q[q,:] . K[k,:]  (only tiles with k0 <= q0)
// Whole D=64 staged once; 128x128 tile; 8 warps (2x4), warp tile 64x32.
// No masking: upper-triangle entries inside diagonal tiles are garbage that
// softmax never reads; fully-masked tiles are never written.
// ---------------------------------------------------------------------------
__global__ __launch_bounds__(256) void scores_tf32(float* __restrict__ S)
{
    if (blockIdx.x > blockIdx.y) return;       // fully masked tile: no work
    extern __shared__ uint32_t sm[];
    uint32_t* Qs = sm;                // [128][68]
    uint32_t* Ks = sm + 128 * 68;     // [128][68]

    const int bh = blockIdx.z;
    const int b = bh / Hh, h = bh % Hh;
    const int q0 = blockIdx.y * 128;
    const int k0t = blockIdx.x * 128;
    float* Sb = S + (size_t)bh * Tt * Tt;

    const int tid = threadIdx.x;
    const int wid = tid >> 5, lane = tid & 31;
    const int g = lane >> 2, tg = lane & 3;
    const int warp_m = wid & 1, warp_n = wid >> 1;

    const float* Qb = g_qkv + (size_t)(b * Tt + q0) * C3 + h * Dd;
    const float* Kb = g_qkv + (size_t)(b * Tt + k0t) * C3 + Cc + h * Dd;

    // stage Q and K tiles (128 x 64 each)
#pragma unroll
    for (int i = 0; i < 8; i++) {
        int f = tid + i * 256;
        int m = f >> 4, kq = (f & 15) * 4;
        float4 qv = *(const float4*)(Qb + (size_t)m * C3 + kq);
        Qs[m * 68 + kq + 0] = f2tf(qv.x);
        Qs[m * 68 + kq + 1] = f2tf(qv.y);
        Qs[m * 68 + kq + 2] = f2tf(qv.z);
        Qs[m * 68 + kq + 3] = f2tf(qv.w);
        float4 kv = *(const float4*)(Kb + (size_t)m * C3 + kq);
        Ks[m * 68 + kq + 0] = f2tf(kv.x);
        Ks[m * 68 + kq + 1] = f2tf(kv.y);
        Ks[m * 68 + kq + 2] = f2tf(kv.z);
        Ks[m * 68 + kq + 3] = f2tf(kv.w);
    }
    __syncthreads();

    float acc[4][4][4] = {};
#pragma unroll
    for (int ks = 0; ks < 64; ks += 8) {
        uint32_t af[4][4], bf[4][2];
#pragma unroll
        for (int mi = 0; mi < 4; mi++) {
            int m = warp_m * 64 + mi * 16;
            af[mi][0] = Qs[(m + g) * 68 + ks + tg];
            af[mi][1] = Qs[(m + g + 8) * 68 + ks + tg];
            af[mi][2] = Qs[(m + g) * 68 + ks + tg + 4];
            af[mi][3] = Qs[(m + g + 8) * 68 + ks + tg + 4];
        }
#pragma unroll
        for (int ni = 0; ni < 4; ni++) {
            int n = warp_n * 32 + ni * 8;
            bf[ni][0] = Ks[(n + g) * 68 + ks + tg];
            bf[ni][1] = Ks[(n + g) * 68 + ks + tg + 4];
        }
#pragma unroll
        for (int mi = 0; mi < 4; mi++)
#pragma unroll
            for (int ni = 0; ni < 4; ni++) mma8(acc[mi][ni], af[mi], bf[ni]);
    }

    const float scale = 0.125f;
#pragma unroll
    for (int mi = 0; mi < 4; mi++) {
#pragma unroll
        for (int ni = 0; ni < 4; ni++) {
            int q = q0 + warp_m * 64 + mi * 16 + g;
            int n = k0t + warp_n * 32 + ni * 8 + tg * 2;
            float2 o0 = {acc[mi][ni][0] * scale, acc[mi][ni][1] * scale};
            float2 o1 = {acc[mi][ni][2] * scale, acc[mi][ni][3] * scale};
            *(float2*)(Sb + (size_t)q * Tt + n) = o0;
            *(float2*)(Sb + (size_t)(q + 8) * Tt + n) = o1;
        }
    }
}

// ---------------------------------------------------------------------------
// Variable-length causal softmax: row q reads only k <= q, writes normalized
// probs there and exact zeros for k > q.
// ---------------------------------------------------------------------------
__global__ __launch_bounds__(256) void softmax_causal(float* __restrict__ S)
{
    const size_t row = blockIdx.x;
    const int q = (int)(row % Tt);
    const int len = q + 1;
    float* p = S + row * (size_t)Tt;
    const int tid = threadIdx.x;
    __shared__ float red[8];

    float v[8];
    int cnt = 0;
    float mx = -INFINITY;
    for (int i = tid; i < len; i += 256) {
        v[cnt] = p[i];
        mx = fmaxf(mx, v[cnt]);
        cnt++;
    }
#pragma unroll
    for (int o = 16; o; o >>= 1) mx = fmaxf(mx, __shfl_xor_sync(0xffffffffu, mx, o));
    if ((tid & 31) == 0) red[tid >> 5] = mx;
    __syncthreads();
    float rowmax = red[0];
#pragma unroll
    for (int w = 1; w < 8; w++) rowmax = fmaxf(rowmax, red[w]);
    __syncthreads();

    float s = 0.f;
    for (int j = 0; j < cnt; j++) {
        v[j] = __expf(v[j] - rowmax);
        s += v[j];
    }
#pragma unroll
    for (int o = 16; o; o >>= 1) s += __shfl_xor_sync(0xffffffffu, s, o);
    if ((tid & 31) == 0) red[tid >> 5] = s;
    __syncthreads();
    float rowsum = 0.f;
#pragma unroll
    for (int w = 0; w < 8; w++) rowsum += red[w];
    const float inv = 1.0f / rowsum;

    cnt = 0;
    for (int i = tid; i < len; i += 256) p[i] = v[cnt++] * inv;
    // zero the masked tail
    for (int i = len + tid; i < Tt; i += 256) p[i] = 0.f;
}

// ---------------------------------------------------------------------------
// PV: attnv[b,q,h,:] = sum_k P[bh,q,k] * V[b,k,h,:]
// Block 128q x 64d, BK=16, causal-truncated k loop.
// 8 warps (4 m x 2 n), warp tile 32x32.
// ---------------------------------------------------------------------------
__global__ __launch_bounds__(256) void pv_tf32(const float* __restrict__ S)
{
    __shared__ uint32_t Ps[128 * 20];   // [m][k] stride 20
    __shared__ uint32_t Vs[16 * 64];    // [k][n ^ ((k&3)<<3)]

    const int q0 = blockIdx.x * 128;
    const int bh = blockIdx.y;
    const int b = bh / Hh, h = bh % Hh;
    const int tid = threadIdx.x;
    const int wid = tid >> 5, lane = tid & 31;
    const int g = lane >> 2, tg = lane & 3;
    const int warp_m = wid >> 1, warp_n = wid & 1;

    const float* Sb = S + (size_t)bh * Tt * Tt + (size_t)q0 * Tt;
    const float* Vb = g_qkv + (size_t)(b * Tt) * C3 + 2 * Cc + h * Dd;

    float acc[2][4][4] = {};
    const int kmax = q0 + 128;

    for (int k0 = 0; k0 < kmax; k0 += 16) {
        // stage P tile 128x16
#pragma unroll
        for (int i = 0; i < 2; i++) {
            int f = tid + i * 256;
            int m = f >> 2, kq = (f & 3) * 4;
            float4 v = *(const float4*)(Sb + (size_t)m * Tt + k0 + kq);
            Ps[m * 20 + kq + 0] = f2tf(v.x);
            Ps[m * 20 + kq + 1] = f2tf(v.y);
            Ps[m * 20 + kq + 2] = f2tf(v.z);
            Ps[m * 20 + kq + 3] = f2tf(v.w);
        }
        // stage V tile 16x64
        {
            int k = tid >> 4, nq = (tid & 15) * 4;
            float4 v = *(const float4*)(Vb + (size_t)(k0 + k) * C3 + nq);
            int nx = nq ^ ((k & 3) << 3);
            Vs[k * 64 + nx + 0] = f2tf(v.x);
            Vs[k * 64 + nx + 1] = f2tf(v.y);
            Vs[k * 64 + nx + 2] = f2tf(v.z);
            Vs[k * 64 + nx + 3] = f2tf(v.w);
        }
        __syncthreads();

#pragma unroll
        for (int ks = 0; ks < 16; ks += 8) {
            uint32_t af[2][4], bf[4][2];
#pragma unroll
            for (int mi = 0; mi < 2; mi++) {
                int m = warp_m * 32 + mi * 16;
                af[mi][0] = Ps[(m + g) * 20 + ks + tg];
                af[mi][1] = Ps[(m + g + 8) * 20 + ks + tg];
                af[mi][2] = Ps[(m + g) * 20 + ks + tg + 4];
                af[mi][3] = Ps[(m + g + 8) * 20 + ks + tg + 4];
            }
            const int xr = tg << 3;
#pragma unroll
            for (int ni = 0; ni < 4; ni++) {
                int n = warp_n * 32 + ni * 8;
                bf[ni][0] = Vs[(ks + tg) * 64 + ((n + g) ^ xr)];
                bf[ni][1] = Vs[(ks + tg + 4) * 64 + ((n + g) ^ xr)];
            }
#pragma unroll
            for (int mi = 0; mi < 2; mi++)
#pragma unroll
                for (int ni = 0; ni < 4; ni++) mma8(acc[mi][ni], af[mi], bf[ni]);
        }
        __syncthreads();
    }

#pragma unroll
    for (int mi = 0; mi < 2; mi++) {
#pragma unroll
        for (int ni = 0; ni < 4; ni++) {
            int q = q0 + warp_m * 32 + mi * 16 + g;
            int n = warp_n * 32 + ni * 8 + tg * 2;
            float* dst0 = g_attnv + (size_t)(b * Tt + q) * Cc + h * Dd + n;
            float* dst1 = g_attnv + (size_t)(b * Tt + q + 8) * Cc + h * Dd + n;
            *(float2*)dst0 = {acc[mi][ni][0], acc[mi][ni][1]};
            *(float2*)dst1 = {acc[mi][ni][2], acc[mi][ni][3]};
        }
    }
}

// ---------------------------------------------------------------------------
extern "C" void kernel_launch(void* const* d_in, const int* in_sizes, int n_in,
                              void* d_out, int out_size)
{
    const float* x     = (const float*)d_in[0];
    const float* w_qkv = (const float*)d_in[1];
    const float* b_qkv = (const float*)d_in[2];
    const float* w_o   = (const float*)d_in[3];
    const float* b_o   = (const float*)d_in[4];

    float* out   = (float*)d_out;
    float* attnw = out + (size_t)Mrows * Cc;   // [o | attn_w]

    float* qkv_ptr   = nullptr;
    float* attnv_ptr = nullptr;
    cudaGetSymbolAddress((void**)&qkv_ptr,   g_qkv);
    cudaGetSymbolAddress((void**)&attnv_ptr, g_attnv);

    static bool attr_set = false;
    const int scores_smem = 2 * 128 * 68 * 4;   // 69632 bytes
    if (!attr_set) {
        cudaFuncSetAttribute(scores_tf32, cudaFuncAttributeMaxDynamicSharedMemorySize,
                             scores_smem);
        attr_set = true;
    }

    // 1) QKV projection
    {
        dim3 grid(C3 / 128, Mrows / 128);
        gemm_nn_tf32<<<grid, 256>>>(x, Cc, w_qkv, C3, b_qkv, qkv_ptr, C3, Cc);
    }
    // 2) Scores (lower-triangular tiles only)
    {
        dim3 grid(Tt / 128, Tt / 128, BH);
        scores_tf32<<<grid, 256, scores_smem>>>(attnw);
    }
    // 3) Causal softmax (reads k<=q, zero-fills tail)
    {
        softmax_causal<<<(unsigned)(BH * Tt), 256>>>(attnw);
    }
    // 4) P @ V
    {
        dim3 grid(Tt / 128, BH);
        pv_tf32<<<grid, 256>>>(attnw);
    }
    // 5) Output projection
    {
        dim3 grid(Cc / 128, Mrows / 128);
        gemm_nn_tf32<<<grid, 256>>>(attnv_ptr, Cc, w_o, Cc, b_o, out, Cc, Cc);
    }
}

// round 4
// speedup vs baseline: 2.7919x; 1.2109x over previous
#include <cuda_runtime.h>
#include <math.h>
#include <stdint.h>

// Problem constants
constexpr int Bb = 2;
constexpr int Tt = 2048;
constexpr int Cc = 1024;
constexpr int Hh = 16;
constexpr int Dd = 64;
constexpr int Mrows = Bb * Tt;        // 4096
constexpr int C3 = 3 * Cc;            // 3072
constexpr int BH = Bb * Hh;           // 32

// Device scratch (allocation-free rule: __device__ globals)
__device__ float g_qkv[(size_t)Mrows * C3];    // [4096, 3072]
__device__ float g_attnv[(size_t)Mrows * Cc];  // [4096, 1024]
__device__ float g_tilestats[(size_t)BH * Tt * 16 * 2]; // per (row, ktile): max, expsum
__device__ float g_rowstats[(size_t)BH * Tt * 2];       // per row: max, 1/sum

// ---------------------------------------------------------------------------
// helpers
// ---------------------------------------------------------------------------
__device__ __forceinline__ uint32_t f2tf(float f) {
    uint32_t u;
    asm("cvt.rna.tf32.f32 %0, %1;" : "=r"(u) : "f"(f));
    return u;
}

__device__ __forceinline__ void mma8(float* c, const uint32_t* a, const uint32_t* b) {
    asm volatile(
        "mma.sync.aligned.m16n8k8.row.col.f32.tf32.tf32.f32 "
        "{%0,%1,%2,%3},{%4,%5,%6,%7},{%8,%9},{%0,%1,%2,%3};"
        : "+f"(c[0]), "+f"(c[1]), "+f"(c[2]), "+f"(c[3])
        : "r"(a[0]), "r"(a[1]), "r"(a[2]), "r"(a[3]), "r"(b[0]), "r"(b[1]));
}

__device__ __forceinline__ void cpasync16(uint32_t saddr, const void* gptr) {
    asm volatile("cp.async.ca.shared.global [%0], [%1], 16;\n" ::"r"(saddr), "l"(gptr));
}

// ---------------------------------------------------------------------------
// Dense NN GEMM: C[M,N] = A[M,K] @ B[K,N] + bias[N]  (tf32, cp.async 3-stage)
// Block 128x128, BK=16, 8 warps (2m x 4n), warp tile 64x32.
// ---------------------------------------------------------------------------
__global__ __launch_bounds__(256, 2) void gemm_nn_tf32(
    const float* __restrict__ A, int lda,
    const float* __restrict__ Bm, int ldb,
    const float* __restrict__ bias,
    float* __restrict__ Cm, int ldc, int Kd)
{
    extern __shared__ float sh[];
    constexpr int STG_F = 128 * 20 + 16 * 128;  // floats per stage

    const int tid = threadIdx.x;
    const int wid = tid >> 5, lane = tid & 31;
    const int g = lane >> 2, tg = lane & 3;
    const int warp_m = wid & 1, warp_n = wid >> 1;
    const int row0 = blockIdx.y * 128;
    const int col0 = blockIdx.x * 128;

    const uint32_t shbase = (uint32_t)__cvta_generic_to_shared(sh);

    auto issue = [&](int s, int k0) {
#pragma unroll
        for (int i = 0; i < 2; i++) {
            int c = tid + i * 256;
            int m = c >> 2, kq = (c & 3) * 4;
            cpasync16(shbase + (s * STG_F + m * 20 + kq) * 4,
                      A + (size_t)(row0 + m) * lda + k0 + kq);
        }
#pragma unroll
        for (int i = 0; i < 2; i++) {
            int c = tid + i * 256;
            int k = c >> 5, nq = (c & 31) * 4;
            int nx = nq ^ ((k & 3) << 3);
            cpasync16(shbase + (s * STG_F + 128 * 20 + k * 128 + nx) * 4,
                      Bm + (size_t)(k0 + k) * ldb + col0 + nq);
        }
        asm volatile("cp.async.commit_group;\n");
    };

    const int nIter = Kd / 16;
    issue(0, 0);
    issue(1, 16);

    float acc[4][4][4] = {};

    for (int j = 0; j < nIter; j++) {
        // TAIL FIX: on the last iteration the stage we read belongs to the
        // NEWEST committed group; wait_group 1 would let it stay in flight.
        if (j == nIter - 1) {
            asm volatile("cp.async.wait_group 0;\n");
        } else {
            asm volatile("cp.async.wait_group 1;\n");
        }
        __syncthreads();
        const float* Asj = sh + (j % 3) * STG_F;
        const float* Bsj = Asj + 128 * 20;
#pragma unroll
        for (int ks = 0; ks < 16; ks += 8) {
            uint32_t af[4][4], bf[4][2];
#pragma unroll
            for (int mi = 0; mi < 4; mi++) {
                int m = warp_m * 64 + mi * 16;
                af[mi][0] = f2tf(Asj[(m + g) * 20 + ks + tg]);
                af[mi][1] = f2tf(Asj[(m + g + 8) * 20 + ks + tg]);
                af[mi][2] = f2tf(Asj[(m + g) * 20 + ks + tg + 4]);
                af[mi][3] = f2tf(Asj[(m + g + 8) * 20 + ks + tg + 4]);
            }
            const int xr = tg << 3;
#pragma unroll
            for (int ni = 0; ni < 4; ni++) {
                int n = warp_n * 32 + ni * 8;
                bf[ni][0] = f2tf(Bsj[(ks + tg) * 128 + ((n + g) ^ xr)]);
                bf[ni][1] = f2tf(Bsj[(ks + tg + 4) * 128 + ((n + g) ^ xr)]);
            }
#pragma unroll
            for (int mi = 0; mi < 4; mi++)
#pragma unroll
                for (int ni = 0; ni < 4; ni++) mma8(acc[mi][ni], af[mi], bf[ni]);
        }
        if (j + 2 < nIter) issue((j + 2) % 3, (j + 2) * 16);
    }

#pragma unroll
    for (int mi = 0; mi < 4; mi++) {
#pragma unroll
        for (int ni = 0; ni < 4; ni++) {
            int m = row0 + warp_m * 64 + mi * 16 + g;
            int n = col0 + warp_n * 32 + ni * 8 + tg * 2;
            float2 o0 = {acc[mi][ni][0] + bias[n], acc[mi][ni][1] + bias[n + 1]};
            float2 o1 = {acc[mi][ni][2] + bias[n], acc[mi][ni][3] + bias[n + 1]};
            *(float2*)(Cm + (size_t)m * ldc + n) = o0;
            *(float2*)(Cm + (size_t)(m + 8) * ldc + n) = o1;
        }
    }
}

// ---------------------------------------------------------------------------
// Scores + per-tile softmax stats.
// Lower/diag tiles: S = scale*QK^T (diag: -inf above diagonal), write S and
// per-(row,tile) (max, expsum) stats. Upper tiles: write zeros (final output).
// ---------------------------------------------------------------------------
__global__ __launch_bounds__(256, 2) void scores_tf32(float* __restrict__ S)
{
    const int bh = blockIdx.z;
    const int q0 = blockIdx.y * 128;
    const int k0t = blockIdx.x * 128;
    float* Sb = S + (size_t)bh * Tt * Tt;
    const int tid = threadIdx.x;

    if (blockIdx.x > blockIdx.y) {
        // fully masked tile: final value is exactly 0
        const float4 z = {0.f, 0.f, 0.f, 0.f};
#pragma unroll
        for (int i = 0; i < 16; i++) {
            int f = i * 256 + tid;
            int r = f >> 5, c = (f & 31) * 4;
            *(float4*)(Sb + (size_t)(q0 + r) * Tt + k0t + c) = z;
        }
        return;
    }

    extern __shared__ uint32_t sm[];
    uint32_t* Qs = sm;                // [128][68]
    uint32_t* Ks = sm + 128 * 68;     // [128][68]
    __shared__ float sred[128][4];
    __shared__ float sredm[128];

    const int b = bh / Hh, h = bh % Hh;
    const int wid = tid >> 5, lane = tid & 31;
    const int g = lane >> 2, tg = lane & 3;
    const int warp_m = wid & 1, warp_n = wid >> 1;

    const float* Qb = g_qkv + (size_t)(b * Tt + q0) * C3 + h * Dd;
    const float* Kb = g_qkv + (size_t)(b * Tt + k0t) * C3 + Cc + h * Dd;

#pragma unroll
    for (int i = 0; i < 8; i++) {
        int f = tid + i * 256;
        int m = f >> 4, kq = (f & 15) * 4;
        float4 qv = *(const float4*)(Qb + (size_t)m * C3 + kq);
        Qs[m * 68 + kq + 0] = f2tf(qv.x);
        Qs[m * 68 + kq + 1] = f2tf(qv.y);
        Qs[m * 68 + kq + 2] = f2tf(qv.z);
        Qs[m * 68 + kq + 3] = f2tf(qv.w);
        float4 kv = *(const float4*)(Kb + (size_t)m * C3 + kq);
        Ks[m * 68 + kq + 0] = f2tf(kv.x);
        Ks[m * 68 + kq + 1] = f2tf(kv.y);
        Ks[m * 68 + kq + 2] = f2tf(kv.z);
        Ks[m * 68 + kq + 3] = f2tf(kv.w);
    }
    __syncthreads();

    float acc[4][4][4] = {};
#pragma unroll
    for (int ks = 0; ks < 64; ks += 8) {
        uint32_t af[4][4], bf[4][2];
#pragma unroll
        for (int mi = 0; mi < 4; mi++) {
            int m = warp_m * 64 + mi * 16;
            af[mi][0] = Qs[(m + g) * 68 + ks + tg];
            af[mi][1] = Qs[(m + g + 8) * 68 + ks + tg];
            af[mi][2] = Qs[(m + g) * 68 + ks + tg + 4];
            af[mi][3] = Qs[(m + g + 8) * 68 + ks + tg + 4];
        }
#pragma unroll
        for (int ni = 0; ni < 4; ni++) {
            int n = warp_n * 32 + ni * 8;
            bf[ni][0] = Ks[(n + g) * 68 + ks + tg];
            bf[ni][1] = Ks[(n + g) * 68 + ks + tg + 4];
        }
#pragma unroll
        for (int mi = 0; mi < 4; mi++)
#pragma unroll
            for (int ni = 0; ni < 4; ni++) mma8(acc[mi][ni], af[mi], bf[ni]);
    }

    // scale + diag mask (upper of diag tile -> -inf), then write S
    const float scale = 0.125f;
    const bool diag = (blockIdx.x == blockIdx.y);
    const float NEG = -INFINITY;
#pragma unroll
    for (int mi = 0; mi < 4; mi++) {
        int r0 = warp_m * 64 + mi * 16 + g;      // tile-local rows r0, r0+8
#pragma unroll
        for (int ni = 0; ni < 4; ni++) {
            int n0 = warp_n * 32 + ni * 8 + tg * 2;  // tile-local cols n0, n0+1
            float* a = acc[mi][ni];
            a[0] *= scale; a[1] *= scale; a[2] *= scale; a[3] *= scale;
            if (diag) {
                if (n0 > r0)     a[0] = NEG;
                if (n0 + 1 > r0) a[1] = NEG;
                if (n0 > r0 + 8)     a[2] = NEG;
                if (n0 + 1 > r0 + 8) a[3] = NEG;
            }
            float2 o0 = {a[0], a[1]};
            float2 o1 = {a[2], a[3]};
            *(float2*)(Sb + (size_t)(q0 + r0) * Tt + k0t + n0) = o0;
            *(float2*)(Sb + (size_t)(q0 + r0 + 8) * Tt + k0t + n0) = o1;
        }
    }

    // ---- per-tile row stats ----
    float mx[4][2];
#pragma unroll
    for (int mi = 0; mi < 4; mi++) {
        float m0 = -INFINITY, m1 = -INFINITY;
#pragma unroll
        for (int ni = 0; ni < 4; ni++) {
            m0 = fmaxf(m0, fmaxf(acc[mi][ni][0], acc[mi][ni][1]));
            m1 = fmaxf(m1, fmaxf(acc[mi][ni][2], acc[mi][ni][3]));
        }
        m0 = fmaxf(m0, __shfl_xor_sync(0xffffffffu, m0, 1));
        m0 = fmaxf(m0, __shfl_xor_sync(0xffffffffu, m0, 2));
        m1 = fmaxf(m1, __shfl_xor_sync(0xffffffffu, m1, 1));
        m1 = fmaxf(m1, __shfl_xor_sync(0xffffffffu, m1, 2));
        mx[mi][0] = m0; mx[mi][1] = m1;
    }
    if (tg == 0) {
#pragma unroll
        for (int mi = 0; mi < 4; mi++) {
            sred[warp_m * 64 + mi * 16 + g][warp_n] = mx[mi][0];
            sred[warp_m * 64 + mi * 16 + g + 8][warp_n] = mx[mi][1];
        }
    }
    __syncthreads();
    if (tid < 128) {
        float m4 = fmaxf(fmaxf(sred[tid][0], sred[tid][1]),
                         fmaxf(sred[tid][2], sred[tid][3]));
        sredm[tid] = m4;
    }
    __syncthreads();
#pragma unroll
    for (int mi = 0; mi < 4; mi++) {
        float rm0 = sredm[warp_m * 64 + mi * 16 + g];
        float rm1 = sredm[warp_m * 64 + mi * 16 + g + 8];
        float s0 = 0.f, s1 = 0.f;
#pragma unroll
        for (int ni = 0; ni < 4; ni++) {
            s0 += __expf(acc[mi][ni][0] - rm0) + __expf(acc[mi][ni][1] - rm0);
            s1 += __expf(acc[mi][ni][2] - rm1) + __expf(acc[mi][ni][3] - rm1);
        }
        s0 += __shfl_xor_sync(0xffffffffu, s0, 1);
        s0 += __shfl_xor_sync(0xffffffffu, s0, 2);
        s1 += __shfl_xor_sync(0xffffffffu, s1, 1);
        s1 += __shfl_xor_sync(0xffffffffu, s1, 2);
        mx[mi][0] = s0; mx[mi][1] = s1;
    }
    __syncthreads();
    if (tg == 0) {
#pragma unroll
        for (int mi = 0; mi < 4; mi++) {
            sred[warp_m * 64 + mi * 16 + g][warp_n] = mx[mi][0];
            sred[warp_m * 64 + mi * 16 + g + 8][warp_n] = mx[mi][1];
        }
    }
    __syncthreads();
    if (tid < 128) {
        float s4 = sred[tid][0] + sred[tid][1] + sred[tid][2] + sred[tid][3];
        size_t idx = (((size_t)bh * Tt + q0 + tid) * 16 + (k0t >> 7)) * 2;
        g_tilestats[idx] = sredm[tid];
        g_tilestats[idx + 1] = s4;
    }
}

// ---------------------------------------------------------------------------
// Combine tile stats -> per-row (max, 1/sum)
// ---------------------------------------------------------------------------
__global__ __launch_bounds__(256) void rowreduce_kernel()
{
    const int r = blockIdx.x * 256 + threadIdx.x;    // 0..BH*Tt-1
    const int q = r & (Tt - 1);
    const int nt = (q >> 7) + 1;
    const float* st = g_tilestats + (size_t)r * 32;
    float m = -INFINITY;
    for (int kt = 0; kt < nt; kt++) m = fmaxf(m, st[kt * 2]);
    float l = 0.f;
    for (int kt = 0; kt < nt; kt++) l += st[kt * 2 + 1] * __expf(st[kt * 2] - m);
    g_rowstats[(size_t)r * 2] = m;
    g_rowstats[(size_t)r * 2 + 1] = 1.0f / l;
}

// ---------------------------------------------------------------------------
// PV with fused normalization: reads raw S, computes p = exp(s-m)*inv,
// writes p in place (final attn_w), accumulates P@V.
// Block 128q x 64d, BK=16, register double buffering. 8 warps (4m x 2n).
// ---------------------------------------------------------------------------
__global__ __launch_bounds__(256, 2) void pv_tf32(float* __restrict__ S)
{
    __shared__ float Ps[2][128 * 20];
    __shared__ float Vs[2][16 * 64];
    __shared__ float srm[128], sri[128];

    const int q0 = blockIdx.x * 128;
    const int bh = blockIdx.y;
    const int b = bh / Hh, h = bh % Hh;
    const int tid = threadIdx.x, wid = tid >> 5, lane = tid & 31;
    const int g = lane >> 2, tg = lane & 3;
    const int warp_m = wid >> 1, warp_n = wid & 1;

    if (tid < 128) {
        size_t rs = ((size_t)bh * Tt + q0 + tid) * 2;
        srm[tid] = g_rowstats[rs];
        sri[tid] = g_rowstats[rs + 1];
    }
    __syncthreads();

    float* Sb = S + (size_t)bh * Tt * Tt + (size_t)q0 * Tt;
    const float* Vb = g_qkv + (size_t)(b * Tt) * C3 + 2 * Cc + h * Dd;

    const int pr0 = tid >> 2, pr1 = 64 + (tid >> 2);
    const int pkq = (tid & 3) * 4;
    const float rm0 = srm[pr0], ri0 = sri[pr0];
    const float rm1 = srm[pr1], ri1 = sri[pr1];
    const int vk = tid >> 4, vnq = (tid & 15) * 4;
    const int vnx = vnq ^ ((vk & 3) << 3);

    const int nIter = (q0 + 128) / 16;
    float4 pa, pb, vv;

    auto ldg = [&](int j) {
        const int k0 = j * 16;
        pa = *(const float4*)(Sb + (size_t)pr0 * Tt + k0 + pkq);
        pb = *(const float4*)(Sb + (size_t)pr1 * Tt + k0 + pkq);
        vv = *(const float4*)(Vb + (size_t)(k0 + vk) * C3 + vnq);
    };
    auto stage = [&](int j, int buf) {
        const int k0 = j * 16;
        float4 p0, p1;
        p0.x = __expf(pa.x - rm0) * ri0;
        p0.y = __expf(pa.y - rm0) * ri0;
        p0.z = __expf(pa.z - rm0) * ri0;
        p0.w = __expf(pa.w - rm0) * ri0;
        p1.x = __expf(pb.x - rm1) * ri1;
        p1.y = __expf(pb.y - rm1) * ri1;
        p1.z = __expf(pb.z - rm1) * ri1;
        p1.w = __expf(pb.w - rm1) * ri1;
        *(float4*)(Sb + (size_t)pr0 * Tt + k0 + pkq) = p0;   // final attn_w
        *(float4*)(Sb + (size_t)pr1 * Tt + k0 + pkq) = p1;
        float* P = Ps[buf];
        P[pr0 * 20 + pkq + 0] = p0.x; P[pr0 * 20 + pkq + 1] = p0.y;
        P[pr0 * 20 + pkq + 2] = p0.z; P[pr0 * 20 + pkq + 3] = p0.w;
        P[pr1 * 20 + pkq + 0] = p1.x; P[pr1 * 20 + pkq + 1] = p1.y;
        P[pr1 * 20 + pkq + 2] = p1.z; P[pr1 * 20 + pkq + 3] = p1.w;
        float* V = Vs[buf];
        V[vk * 64 + vnx + 0] = vv.x; V[vk * 64 + vnx + 1] = vv.y;
        V[vk * 64 + vnx + 2] = vv.z; V[vk * 64 + vnx + 3] = vv.w;
    };

    ldg(0);
    stage(0, 0);
    __syncthreads();

    float acc[2][4][4] = {};
    for (int j = 0; j < nIter; j++) {
        if (j + 1 < nIter) ldg(j + 1);
        const float* Pj = Ps[j & 1];
        const float* Vj = Vs[j & 1];
#pragma unroll
        for (int ks = 0; ks < 16; ks += 8) {
            uint32_t af[2][4], bf[4][2];
#pragma unroll
            for (int mi = 0; mi < 2; mi++) {
                int m = warp_m * 32 + mi * 16;
                af[mi][0] = f2tf(Pj[(m + g) * 20 + ks + tg]);
                af[mi][1] = f2tf(Pj[(m + g + 8) * 20 + ks + tg]);
                af[mi][2] = f2tf(Pj[(m + g) * 20 + ks + tg + 4]);
                af[mi][3] = f2tf(Pj[(m + g + 8) * 20 + ks + tg + 4]);
            }
            const int xr = tg << 3;
#pragma unroll
            for (int ni = 0; ni < 4; ni++) {
                int n = warp_n * 32 + ni * 8;
                bf[ni][0] = f2tf(Vj[(ks + tg) * 64 + ((n + g) ^ xr)]);
                bf[ni][1] = f2tf(Vj[(ks + tg + 4) * 64 + ((n + g) ^ xr)]);
            }
#pragma unroll
            for (int mi = 0; mi < 2; mi++)
#pragma unroll
                for (int ni = 0; ni < 4; ni++) mma8(acc[mi][ni], af[mi], bf[ni]);
        }
        if (j + 1 < nIter) stage(j + 1, (j + 1) & 1);
        __syncthreads();
    }

#pragma unroll
    for (int mi = 0; mi < 2; mi++) {
#pragma unroll
        for (int ni = 0; ni < 4; ni++) {
            int q = q0 + warp_m * 32 + mi * 16 + g;
            int n = warp_n * 32 + ni * 8 + tg * 2;
            float* dst0 = g_attnv + (size_t)(b * Tt + q) * Cc + h * Dd + n;
            float* dst1 = g_attnv + (size_t)(b * Tt + q + 8) * Cc + h * Dd + n;
            *(float2*)dst0 = {acc[mi][ni][0], acc[mi][ni][1]};
            *(float2*)dst1 = {acc[mi][ni][2], acc[mi][ni][3]};
        }
    }
}

// ---------------------------------------------------------------------------
extern "C" void kernel_launch(void* const* d_in, const int* in_sizes, int n_in,
                              void* d_out, int out_size)
{
    const float* x     = (const float*)d_in[0];
    const float* w_qkv = (const float*)d_in[1];
    const float* b_qkv = (const float*)d_in[2];
    const float* w_o   = (const float*)d_in[3];
    const float* b_o   = (const float*)d_in[4];

    float* out   = (float*)d_out;
    float* attnw = out + (size_t)Mrows * Cc;   // [o | attn_w]

    float* qkv_ptr   = nullptr;
    float* attnv_ptr = nullptr;
    cudaGetSymbolAddress((void**)&qkv_ptr,   g_qkv);
    cudaGetSymbolAddress((void**)&attnv_ptr, g_attnv);

    const int gemm_smem   = 3 * (128 * 20 + 16 * 128) * 4;   // 55296
    const int scores_smem = 2 * 128 * 68 * 4;                // 69632
    static bool attr_set = false;
    if (!attr_set) {
        cudaFuncSetAttribute(gemm_nn_tf32, cudaFuncAttributeMaxDynamicSharedMemorySize,
                             gemm_smem);
        cudaFuncSetAttribute(scores_tf32, cudaFuncAttributeMaxDynamicSharedMemorySize,
                             scores_smem);
        attr_set = true;
    }

    // 1) QKV projection
    {
        dim3 grid(C3 / 128, Mrows / 128);
        gemm_nn_tf32<<<grid, 256, gemm_smem>>>(x, Cc, w_qkv, C3, b_qkv, qkv_ptr, C3, Cc);
    }
    // 2) Scores + tile stats (upper tiles -> zeros)
    {
        dim3 grid(Tt / 128, Tt / 128, BH);
        scores_tf32<<<grid, 256, scores_smem>>>(attnw);
    }
    // 3) Row stats combine
    {
        rowreduce_kernel<<<(BH * Tt) / 256, 256>>>();
    }
    // 4) P @ V with fused normalization (writes final attn_w in place)
    {
        dim3 grid(Tt / 128, BH);
        pv_tf32<<<grid, 256>>>(attnw);
    }
    // 5) Output projection
    {
        dim3 grid(Cc / 128, Mrows / 128);
        gemm_nn_tf32<<<grid, 256, gemm_smem>>>(attnv_ptr, Cc, w_o, Cc, b_o, out, Cc, Cc);
    }
}